// round 10
// baseline (speedup 1.0000x reference)
#include <cuda_runtime.h>

#define HID 64
#define NBATCH 256
#define SEQ 4096
#define NG 256   // 4*HID gates

// Scratch (no cudaMalloc allowed).  g_xz has a 4*NG tail pad so the ring
// prefetch can run 4 steps past the end without bounds checks.
__device__ float g_seqA[(size_t)NBATCH * SEQ * HID];          // 256 MB
__device__ float g_seqB[(size_t)NBATCH * SEQ * HID];          // 256 MB
__device__ float g_xz[(size_t)NBATCH * SEQ * NG + 4 * NG];    // 1 GB + pad

typedef unsigned long long ull;

static __device__ __forceinline__ ull pk2(float lo, float hi) {
    ull r;
    asm("mov.b64 %0, {%1,%2};" : "=l"(r) : "f"(lo), "f"(hi));
    return r;
}
static __device__ __forceinline__ void upk2(ull v, float& lo, float& hi) {
    asm("mov.b64 {%0,%1}, %2;" : "=f"(lo), "=f"(hi) : "l"(v));
}
static __device__ __forceinline__ void ffma2(ull& d, ull a, ull b) {
    asm("fma.rn.f32x2 %0, %1, %2, %0;" : "+l"(d) : "l"(a), "l"(b));
}
static __device__ __forceinline__ float ex2f(float x) {
    float r; asm("ex2.approx.f32 %0, %1;" : "=f"(r) : "f"(x)); return r;
}
static __device__ __forceinline__ float rcpf(float x) {
    float r; asm("rcp.approx.f32 %0, %1;" : "=f"(r) : "f"(x)); return r;
}
#define L2E 1.44269504088896f
// tanh(x) = 1 - 2/(2^(2*L2E*x)+1); overflow-safe both directions.
static __device__ __forceinline__ float tanh_f(float x) {
    return fmaf(-2.0f, rcpf(ex2f(x * (2.0f * L2E)) + 1.0f), 1.0f);
}

// gate remap: storage index tid <-> gate row jg = (tid&3)*HID + (tid>>2)

// ---------------------------------------------------------------------------
// xz precompute, DIN = 64 (gate-remapped output), layers 1-2 only.
// ---------------------------------------------------------------------------
__global__ void __launch_bounds__(256)
xz_din64_kernel(const float* __restrict__ in_seq,   // [B,SEQ,64]
                const float* __restrict__ Wih,      // [256,64]
                const float* __restrict__ bih,
                const float* __restrict__ bhh,
                float* __restrict__ xz) {
    __shared__ __align__(16) float sin_[32][HID];   // 8 KB
    const int tid = threadIdx.x;
    const int jg  = (tid & 3) * HID + (tid >> 2);
    const int b   = blockIdx.y;
    const int t0  = blockIdx.x * 32;

    const float* src = in_seq + ((size_t)b * SEQ + t0) * HID;
#pragma unroll
    for (int k = 0; k < 8; ++k)
        ((float*)sin_)[tid + k * 256] = src[tid + k * 256];

    ull wi[32];
#pragma unroll
    for (int p = 0; p < 32; ++p)
        wi[p] = pk2(Wih[jg * HID + 2 * p], Wih[jg * HID + 2 * p + 1]);
    const float bias = bih[jg] + bhh[jg];
    __syncthreads();

    float* o = xz + ((size_t)b * SEQ + t0) * NG + tid;
#pragma unroll 4
    for (int tt = 0; tt < 32; ++tt) {
        const ulonglong2* v = (const ulonglong2*)&sin_[tt][0];
        ull a0 = pk2(bias, 0.0f), a1 = 0ULL;
#pragma unroll
        for (int p = 0; p < 16; ++p) {
            ulonglong2 q = v[p];
            ffma2(a0, wi[2 * p], q.x);
            ffma2(a1, wi[2 * p + 1], q.y);
        }
        float l0, l1, h0, h1;
        upk2(a0, l0, h0); upk2(a1, l1, h1);
        o[(size_t)tt * NG] = (l0 + h0) + (l1 + h1);
    }
}

// ---------------------------------------------------------------------------
// Recurrent kernel.  1 batch/CTA, 256 CTAs x 256 threads, 2 CTAs/SM.
// Thread (u = tid>>2, q = tid&3): partial dots of all 4 gates of unit u over
// h-chunk q (4 LDS.128), quad reduce-scatter (2 shuffles) leaves lane q
// holding gate-q preactivation; unified activation (1 ex2 + 1 rcp); quad
// gather (4 shuffles); 1 barrier/step.  h double-buffered, padded smem.
// ANTI-PHASE STAGGER: odd CTAs spin ~400 cyc once before loop entry so the
// two co-resident CTAs on an SM interleave issue-heavy GEMV phases with the
// other's latency-heavy shuffle/MUFU tail instead of phase-colliding.
// ---------------------------------------------------------------------------
template <bool DIN1>
__global__ void __launch_bounds__(256, 2)
lstm_rec_kernel(const float* __restrict__ x,        // DIN1: [B,SEQ]
                const float* __restrict__ xz,       // !DIN1: [B,SEQ,256] remapped
                const float* __restrict__ Wih,      // DIN1: [256,1]
                const float* __restrict__ bih,
                const float* __restrict__ bhh,
                const float* __restrict__ Whh,      // [256,64]
                float* __restrict__ out_seq,        // [B,SEQ,64]
                float* __restrict__ d_out,
                int layer) {
    __shared__ __align__(16) float sh[2][80];       // 4 chunks * stride 20

    const int tid = threadIdx.x;
    const int b   = blockIdx.x;
    const int u   = tid >> 2;
    const int q   = tid & 3;
    const int jg  = q * HID + u;

    // weights: 4 gate rows of unit u, columns [16q, 16q+16)
    ull w[32];
#pragma unroll
    for (int g = 0; g < 4; ++g) {
        const int row = g * HID + u;
#pragma unroll
        for (int m = 0; m < 8; ++m)
            w[g * 8 + m] = pk2(Whh[row * HID + 16 * q + 2 * m],
                               Whh[row * HID + 16 * q + 2 * m + 1]);
    }

    // input-contribution state
    float wx = 0.0f, bias = 0.0f;
    const float* xp = nullptr;       // DIN1 input stream
    const float* zpref = nullptr;    // !DIN1 prefetch pointer (t+4 row)
    float ring[4];
    if (DIN1) {
        wx   = Wih[jg];
        bias = bih[jg] + bhh[jg];
        xp = x + (size_t)b * SEQ;
#pragma unroll
        for (int d = 0; d < 4; ++d) ring[d] = xp[d];
    } else {
        const float* z = xz + (size_t)b * SEQ * NG + tid;
#pragma unroll
        for (int d = 0; d < 4; ++d) ring[d] = z[(size_t)d * NG];
        zpref = z + (size_t)4 * NG;
    }

    // activation constants: lane's own gate is tanh iff q==2
    const float sA = (q == 2) ? 2.0f : 1.0f;
    const float kA = sA * L2E;
    const int lbase = (tid & 31) & ~3;
    const bool lowq = (q < 2);
    const bool oddq = (q & 1);

    float c = 0.0f, hlast = 0.0f;
    if (tid < 160) sh[tid / 80][tid % 80] = 0.0f;
    __syncthreads();

    // anti-phase stagger: odd CTAs delay ~half a step period (one-time;
    // identical loop periods preserve the offset thereafter)
    if (b & 1) {
        const unsigned long long start = clock64();
        while (clock64() - start < 400ULL) {}
    }
    __syncthreads();

#pragma unroll 4
    for (int t = 0; t < SEQ; ++t) {
        const int par  = t & 1;                     // static under unroll
        const int slot = t & 3;

        // ---- partial dots: 4 gates over h-chunk q ----
        const ulonglong2* v = (const ulonglong2*)&sh[par][20 * q];
        ull ac0 = 0ULL, ac1 = 0ULL, ac2 = 0ULL, ac3 = 0ULL;
#pragma unroll
        for (int p = 0; p < 4; ++p) {
            ulonglong2 d = v[p];
            ffma2(ac0, w[0 * 8 + 2 * p], d.x); ffma2(ac0, w[0 * 8 + 2 * p + 1], d.y);
            ffma2(ac1, w[1 * 8 + 2 * p], d.x); ffma2(ac1, w[1 * 8 + 2 * p + 1], d.y);
            ffma2(ac2, w[2 * 8 + 2 * p], d.x); ffma2(ac2, w[2 * 8 + 2 * p + 1], d.y);
            ffma2(ac3, w[3 * 8 + 2 * p], d.x); ffma2(ac3, w[3 * 8 + 2 * p + 1], d.y);
        }
        float pi, pf, pg, po, lo, hi;
        upk2(ac0, lo, hi); pi = lo + hi;
        upk2(ac1, lo, hi); pf = lo + hi;
        upk2(ac2, lo, hi); pg = lo + hi;
        upk2(ac3, lo, hi); po = lo + hi;

        // ---- quad reduce-scatter: lane q ends with gate-q total ----
        float kX = lowq ? pi : pg, kY = lowq ? pf : po;
        float sX = lowq ? pg : pi, sY = lowq ? po : pf;
        kX += __shfl_xor_sync(0xffffffffu, sX, 2, 32);
        kY += __shfl_xor_sync(0xffffffffu, sY, 2, 32);
        float snd = oddq ? kX : kY;
        float tot = (oddq ? kY : kX) + __shfl_xor_sync(0xffffffffu, snd, 1, 32);

        // ---- input contribution + prefetch ----
        float g;
        if (DIN1) {
            g = tot + fmaf(wx, ring[slot], bias);
            const int tp = (t + 4 < SEQ) ? (t + 4) : (SEQ - 1);  // no OOB on input
            ring[slot] = xp[tp];
        } else {
            g = tot + ring[slot];
            ring[slot] = *zpref;                    // padded: no bounds check
            zpref += NG;
        }

        // ---- own-gate activation (branch-free, 1 ex2 + 1 rcp) ----
        const float a = fmaf(-sA, rcpf(ex2f(g * kA) + 1.0f), 1.0f);

        // ---- gather quad activations, pointwise update ----
        const float ai = __shfl_sync(0xffffffffu, a, lbase + 0, 32);
        const float af = __shfl_sync(0xffffffffu, a, lbase + 1, 32);
        const float ag = __shfl_sync(0xffffffffu, a, lbase + 2, 32);
        const float ao = __shfl_sync(0xffffffffu, a, lbase + 3, 32);
        c = fmaf(af, c, ai * ag);
        const float h = ao * tanh_f(c);
        hlast = h;
        if (q == 0) {
            sh[par ^ 1][20 * (u >> 4) + (u & 15)] = h;
            out_seq[((size_t)b * SEQ + t) * HID + u] = h;
        }
        __syncthreads();                            // h(t) visible
    }

    if (q == 0) {
        const size_t yoff = (size_t)NBATCH * SEQ;
        d_out[yoff + (size_t)layer * NBATCH * HID + (size_t)b * HID + u] = hlast;
        d_out[yoff + (size_t)3 * NBATCH * HID + (size_t)layer * NBATCH * HID
              + (size_t)b * HID + u] = c;
    }
}

// ---------------------------------------------------------------------------
// Final linear: y[r] = dot(g_seqA[r,:], Wlin) + blin.
// ---------------------------------------------------------------------------
__global__ void __launch_bounds__(256)
linear_kernel(const float* __restrict__ Wlin,
              const float* __restrict__ blin,
              float* __restrict__ y) {
    const int lane  = threadIdx.x & 31;
    const int warp  = (blockIdx.x * blockDim.x + threadIdx.x) >> 5;
    const int nwarp = (gridDim.x * blockDim.x) >> 5;
    const float w0 = Wlin[lane];
    const float w1 = Wlin[lane + 32];
    const float bl = blin[0];
    const int nrows = NBATCH * SEQ;
    for (int r = warp; r < nrows; r += nwarp) {
        const float* row = g_seqA + (size_t)r * HID;
        float s = row[lane] * w0 + row[lane + 32] * w1;
#pragma unroll
        for (int o = 16; o; o >>= 1) s += __shfl_down_sync(0xffffffffu, s, o);
        if (lane == 0) y[r] = s + bl;
    }
}

extern "C" void kernel_launch(void* const* d_in, const int* in_sizes, int n_in,
                              void* d_out, int out_size) {
    const float* x    = (const float*)d_in[0];
    const float* Wih0 = (const float*)d_in[1];
    const float* Whh0 = (const float*)d_in[2];
    const float* bih0 = (const float*)d_in[3];
    const float* bhh0 = (const float*)d_in[4];
    const float* Wih1 = (const float*)d_in[5];
    const float* Whh1 = (const float*)d_in[6];
    const float* bih1 = (const float*)d_in[7];
    const float* bhh1 = (const float*)d_in[8];
    const float* Wih2 = (const float*)d_in[9];
    const float* Whh2 = (const float*)d_in[10];
    const float* bih2 = (const float*)d_in[11];
    const float* bhh2 = (const float*)d_in[12];
    const float* Wlin = (const float*)d_in[13];
    const float* blin = (const float*)d_in[14];
    float* out = (float*)d_out;

    float* xzp;  cudaGetSymbolAddress((void**)&xzp, g_xz);
    float* sA;   cudaGetSymbolAddress((void**)&sA, g_seqA);
    float* sB;   cudaGetSymbolAddress((void**)&sB, g_seqB);

    // layer 0: fused input path (no xz materialization)
    lstm_rec_kernel<true><<<NBATCH, 256>>>(x, nullptr, Wih0, bih0, bhh0,
                                           Whh0, sA, out, 0);

    xz_din64_kernel<<<dim3(SEQ / 32, NBATCH), 256>>>(sA, Wih1, bih1, bhh1, xzp);
    lstm_rec_kernel<false><<<NBATCH, 256>>>(nullptr, xzp, nullptr, nullptr,
                                            nullptr, Whh1, sB, out, 1);

    xz_din64_kernel<<<dim3(SEQ / 32, NBATCH), 256>>>(sB, Wih2, bih2, bhh2, xzp);
    lstm_rec_kernel<false><<<NBATCH, 256>>>(nullptr, xzp, nullptr, nullptr,
                                            nullptr, Whh2, sA, out, 2);

    linear_kernel<<<1024, 256>>>(Wlin, blin, out);
}